// round 13
// baseline (speedup 1.0000x reference)
#include <cuda_runtime.h>
#include <cuda_fp16.h>
#include <cstdint>
#include <math.h>

#define BB 2
#define SS 2048
#define HH 1024
#define NHEADS 16
#define HDIM 64
#define MTOT (BB*SS)      // 4096
#define NQKV (3*HH)       // 3072

// Scratch (allocation-free rule: __device__ globals)
__device__ __half g_hid_h[(size_t)MTOT * HH];    // 8 MiB
__device__ __half g_wq_h[(size_t)HH * NQKV];     // 6 MiB
__device__ __half g_wd_h[(size_t)HH * HH];       // 2 MiB
__device__ __half g_qkv_h[(size_t)MTOT * NQKV];  // 24 MiB (Q pre-scaled 1/8)
__device__ __half g_ctx_h[(size_t)MTOT * HH];    // 8 MiB
__device__ float g_x[(size_t)MTOT * HH];         // 16 MiB

// ============================================================================
// helpers
// ============================================================================
__device__ __forceinline__ uint32_t smem_u32(const void* p) {
    uint32_t a;
    asm("{ .reg .u64 t; cvta.to.shared.u64 t, %1; cvt.u32.u64 %0, t; }"
        : "=r"(a) : "l"(p));
    return a;
}
__device__ __forceinline__ void cpasync16(uint32_t s, const void* g) {
    asm volatile("cp.async.cg.shared.global [%0], [%1], 16;" :: "r"(s), "l"(g));
}
#define CP_COMMIT() asm volatile("cp.async.commit_group;" ::: "memory")
#define CP_WAIT0()  asm volatile("cp.async.wait_group 0;" ::: "memory")
#define CP_WAIT1()  asm volatile("cp.async.wait_group 1;" ::: "memory")
#define CP_WAIT2()  asm volatile("cp.async.wait_group 2;" ::: "memory")

// pack two f32 -> f16x2 (lo = first arg, hi = second arg)
__device__ __forceinline__ uint32_t pack_f16(float lo, float hi) {
    uint32_t r;
    asm("cvt.rn.f16x2.f32 %0, %1, %2;" : "=r"(r) : "f"(hi), "f"(lo));
    return r;
}
// fp16 m16n8k16, fp32 accumulate (all GEMMs + attention)
__device__ __forceinline__ void mma_f16_f32(float c[4], const uint32_t a[4],
                                            const uint32_t b[2]) {
    asm volatile(
        "mma.sync.aligned.m16n8k16.row.col.f32.f16.f16.f32 "
        "{%0,%1,%2,%3}, {%4,%5,%6,%7}, {%8,%9}, {%0,%1,%2,%3};\n"
        : "+f"(c[0]), "+f"(c[1]), "+f"(c[2]), "+f"(c[3])
        : "r"(a[0]), "r"(a[1]), "r"(a[2]), "r"(a[3]), "r"(b[0]), "r"(b[1]));
}
__device__ __forceinline__ void ldmatrix_x4(uint32_t r[4], uint32_t addr) {
    asm volatile("ldmatrix.sync.aligned.m8n8.x4.shared.b16 {%0,%1,%2,%3}, [%4];"
                 : "=r"(r[0]), "=r"(r[1]), "=r"(r[2]), "=r"(r[3]) : "r"(addr));
}
__device__ __forceinline__ void ldmatrix_x4t(uint32_t r[4], uint32_t addr) {
    asm volatile("ldmatrix.sync.aligned.m8n8.x4.trans.shared.b16 {%0,%1,%2,%3}, [%4];"
                 : "=r"(r[0]), "=r"(r[1]), "=r"(r[2]), "=r"(r[3]) : "r"(addr));
}

// ============================================================================
// prep: single-launch fp32 -> fp16 convert, 4 float4 per thread (MLP=4)
// blocks [0,1024): hidden, [1024,1792): w_qkv, [1792,2048): w_dense
// ============================================================================
__global__ __launch_bounds__(256)
void f2h_all_kernel(const float* __restrict__ hid_f, const float* __restrict__ wq_f,
                    const float* __restrict__ wd_f, __half* __restrict__ hid_h,
                    __half* __restrict__ wq_h, __half* __restrict__ wd_h)
{
    const int b = blockIdx.x;
    const float* in;
    __half* out;
    int rb;
    if (b < 1024)      { in = hid_f; out = hid_h; rb = b; }
    else if (b < 1792) { in = wq_f;  out = wq_h;  rb = b - 1024; }
    else               { in = wd_f;  out = wd_h;  rb = b - 1792; }

    float4 v[4];
#pragma unroll
    for (int i = 0; i < 4; i++)
        v[i] = ((const float4*)in)[(size_t)rb * 1024 + i * 256 + threadIdx.x];
#pragma unroll
    for (int i = 0; i < 4; i++) {
        uint2 o;
        o.x = pack_f16(v[i].x, v[i].y);
        o.y = pack_f16(v[i].z, v[i].w);
        ((uint2*)out)[(size_t)rb * 1024 + i * 256 + threadIdx.x] = o;
    }
}

// ============================================================================
// QKV GEMM: 128x256 CTA tile, BK=64, 256 threads (8 warps as 2x4 of 64x64),
// 4-STAGE cp.async ring — prefetch target (ks+3)&3 != ks&3, issued right
// after the barrier: race-free AND fully overlapped.
// Out fp16, +bias, Q cols (c%192<64) scaled by 0.125.
// ============================================================================
#define AS_STR 72
#define BS_STR 264
#define AS_ELE (128 * AS_STR)
#define BS_ELE (64 * BS_STR)
#define STAGE_ELE (AS_ELE + BS_ELE)            // 26112
#define QKV_SMEM_BYTES (4 * STAGE_ELE * 2)     // 208896

__global__ __launch_bounds__(256)
void gemm_qkv_kernel(const __half* __restrict__ A, const __half* __restrict__ B,
                     const float* __restrict__ bias, __half* __restrict__ Cout,
                     int K, int N)
{
    extern __shared__ __align__(16) __half sh[];

    const int tid = threadIdx.x;
    const int w = tid >> 5, lane = tid & 31;
    const int g = lane >> 2, tig = lane & 3;
    const int wm = w >> 2;
    const int wn = w & 3;
    const int bm = blockIdx.y * 128, bn = blockIdx.x * 256;
    const int nst = K / 64;

    float cf[4][8][4];
#pragma unroll
    for (int mi = 0; mi < 4; mi++)
#pragma unroll
        for (int ni = 0; ni < 8; ni++)
#pragma unroll
            for (int q = 0; q < 4; q++) cf[mi][ni][q] = 0.0f;

    auto load_stage = [&](int st, int ks) {
        __half* As = sh + st * STAGE_ELE;
        __half* Bs = As + AS_ELE;
#pragma unroll
        for (int i = 0; i < 4; i++) {
            int l = tid + i * 256;
            int row = l >> 3, seg = l & 7;
            cpasync16(smem_u32(As + row * AS_STR + seg * 8),
                      A + (size_t)(bm + row) * K + ks * 64 + seg * 8);
        }
#pragma unroll
        for (int i = 0; i < 8; i++) {
            int l = tid + i * 256;
            int row = l >> 5, seg = l & 31;
            cpasync16(smem_u32(Bs + row * BS_STR + seg * 8),
                      B + (size_t)(ks * 64 + row) * N + bn + seg * 8);
        }
    };

    load_stage(0, 0); CP_COMMIT();
    load_stage(1, 1); CP_COMMIT();
    load_stage(2, 2); CP_COMMIT();

    const int l16 = lane & 15;
    const int lhi = (lane >> 4) * 8;

    for (int ks = 0; ks < nst; ks++) {
        if (ks <= nst - 3)      { CP_WAIT2(); }
        else if (ks == nst - 2) { CP_WAIT1(); }
        else                    { CP_WAIT0(); }
        __syncthreads();

        // prefetch into slot (ks+3)&3 — last read at iteration ks-1, all
        // warps past the barrier above: race-free.
        if (ks + 3 < nst) { load_stage((ks + 3) & 3, ks + 3); CP_COMMIT(); }

        const __half* Ab = sh + (ks & 3) * STAGE_ELE;
        const __half* Bb = Ab + AS_ELE;
#pragma unroll
        for (int kc = 0; kc < 4; kc++) {
            uint32_t au[4][4];
#pragma unroll
            for (int mi = 0; mi < 4; mi++)
                ldmatrix_x4(au[mi], smem_u32(Ab + (wm * 64 + mi * 16 + l16) * AS_STR
                                             + kc * 16 + lhi));
            uint32_t bu[8][2];
#pragma unroll
            for (int p = 0; p < 4; p++) {
                uint32_t t4[4];
                ldmatrix_x4t(t4, smem_u32(Bb + (kc * 16 + l16) * BS_STR
                                          + wn * 64 + p * 16 + lhi));
                bu[2 * p][0] = t4[0]; bu[2 * p][1] = t4[1];
                bu[2 * p + 1][0] = t4[2]; bu[2 * p + 1][1] = t4[3];
            }
#pragma unroll
            for (int mi = 0; mi < 4; mi++)
#pragma unroll
                for (int ni = 0; ni < 8; ni++)
                    mma_f16_f32(cf[mi][ni], au[mi], bu[ni]);
        }
    }

#pragma unroll
    for (int mi = 0; mi < 4; mi++) {
        const int r = bm + wm * 64 + mi * 16 + g;
#pragma unroll
        for (int ni = 0; ni < 8; ni++) {
            const int c = bn + wn * 64 + ni * 8 + 2 * tig;
            float v0 = cf[mi][ni][0] + bias[c];
            float v1 = cf[mi][ni][1] + bias[c + 1];
            float v2 = cf[mi][ni][2] + bias[c];
            float v3 = cf[mi][ni][3] + bias[c + 1];
            if ((c % 192) < 64) { v0 *= 0.125f; v1 *= 0.125f; v2 *= 0.125f; v3 *= 0.125f; }
            *(uint32_t*)(Cout + (size_t)r * N + c) = pack_f16(v0, v1);
            *(uint32_t*)(Cout + (size_t)(r + 8) * N + c) = pack_f16(v2, v3);
        }
    }
}

// ============================================================================
// Dense GEMM: 128x128 CTA tile, BK=64, 128 threads (4 warps as 2x2 of 64x64),
// 4-STAGE ring (race-free), full SM coverage (grid 256).
// Out fp32, +bias, +residual.
// ============================================================================
#define DAS_STR 72
#define DBS_STR 136
#define DAS_ELE (128 * DAS_STR)       // 9216
#define DBS_ELE (64 * DBS_STR)        // 8704
#define DSTAGE_ELE (DAS_ELE + DBS_ELE)
#define DENSE_SMEM_BYTES (4 * DSTAGE_ELE * 2)   // 143360

__global__ __launch_bounds__(128)
void gemm_dense_kernel(const __half* __restrict__ A, const __half* __restrict__ B,
                       const float* __restrict__ bias, const float* __restrict__ res,
                       float* __restrict__ Cout, int K, int N)
{
    extern __shared__ __align__(16) __half sh[];

    const int tid = threadIdx.x;
    const int w = tid >> 5, lane = tid & 31;
    const int g = lane >> 2, tig = lane & 3;
    const int wm = w >> 1;
    const int wn = w & 1;
    const int bm = blockIdx.y * 128, bn = blockIdx.x * 128;
    const int nst = K / 64;

    float cf[4][8][4];
#pragma unroll
    for (int mi = 0; mi < 4; mi++)
#pragma unroll
        for (int ni = 0; ni < 8; ni++)
#pragma unroll
            for (int q = 0; q < 4; q++) cf[mi][ni][q] = 0.0f;

    auto load_stage = [&](int st, int ks) {
        __half* As = sh + st * DSTAGE_ELE;
        __half* Bs = As + DAS_ELE;
#pragma unroll
        for (int i = 0; i < 8; i++) {
            int l = tid + i * 128;
            int row = l >> 3, seg = l & 7;
            cpasync16(smem_u32(As + row * DAS_STR + seg * 8),
                      A + (size_t)(bm + row) * K + ks * 64 + seg * 8);
        }
#pragma unroll
        for (int i = 0; i < 8; i++) {
            int l = tid + i * 128;
            int row = l >> 4, seg = l & 15;
            cpasync16(smem_u32(Bs + row * DBS_STR + seg * 8),
                      B + (size_t)(ks * 64 + row) * N + bn + seg * 8);
        }
    };

    load_stage(0, 0); CP_COMMIT();
    load_stage(1, 1); CP_COMMIT();
    load_stage(2, 2); CP_COMMIT();

    const int l16 = lane & 15;
    const int lhi = (lane >> 4) * 8;

    for (int ks = 0; ks < nst; ks++) {
        if (ks <= nst - 3)      { CP_WAIT2(); }
        else if (ks == nst - 2) { CP_WAIT1(); }
        else                    { CP_WAIT0(); }
        __syncthreads();

        if (ks + 3 < nst) { load_stage((ks + 3) & 3, ks + 3); CP_COMMIT(); }

        const __half* Ab = sh + (ks & 3) * DSTAGE_ELE;
        const __half* Bb = Ab + DAS_ELE;
#pragma unroll
        for (int kc = 0; kc < 4; kc++) {
            uint32_t au[4][4];
#pragma unroll
            for (int mi = 0; mi < 4; mi++)
                ldmatrix_x4(au[mi], smem_u32(Ab + (wm * 64 + mi * 16 + l16) * DAS_STR
                                             + kc * 16 + lhi));
            uint32_t bu[8][2];
#pragma unroll
            for (int p = 0; p < 4; p++) {
                uint32_t t4[4];
                ldmatrix_x4t(t4, smem_u32(Bb + (kc * 16 + l16) * DBS_STR
                                          + wn * 64 + p * 16 + lhi));
                bu[2 * p][0] = t4[0]; bu[2 * p][1] = t4[1];
                bu[2 * p + 1][0] = t4[2]; bu[2 * p + 1][1] = t4[3];
            }
#pragma unroll
            for (int mi = 0; mi < 4; mi++)
#pragma unroll
                for (int ni = 0; ni < 8; ni++)
                    mma_f16_f32(cf[mi][ni], au[mi], bu[ni]);
        }
    }

#pragma unroll
    for (int mi = 0; mi < 4; mi++) {
        const int r = bm + wm * 64 + mi * 16 + g;
#pragma unroll
        for (int ni = 0; ni < 8; ni++) {
            const int c = bn + wn * 64 + ni * 8 + 2 * tig;
            const float2 r0 = *(const float2*)(res + (size_t)r * N + c);
            const float2 r1 = *(const float2*)(res + (size_t)(r + 8) * N + c);
            *(float2*)(Cout + (size_t)r * N + c) =
                make_float2(cf[mi][ni][0] + bias[c] + r0.x,
                            cf[mi][ni][1] + bias[c + 1] + r0.y);
            *(float2*)(Cout + (size_t)(r + 8) * N + c) =
                make_float2(cf[mi][ni][2] + bias[c] + r1.x,
                            cf[mi][ni][3] + bias[c + 1] + r1.y);
        }
    }
}

// ============================================================================
// Flash attention (R10/R11-proven, byte-identical — already race-free 4-stage)
// ============================================================================
#define TS 72
#define ATTN_Q_ELE (128 * TS)
#define ATTN_KV_ELE (64 * TS)
#define ATTN_STAGE_ELE (2 * ATTN_KV_ELE)
#define ATTN_SMEM_BYTES ((ATTN_Q_ELE + 4 * ATTN_STAGE_ELE) * 2)  // 92160

__global__ __launch_bounds__(256)
void attn_f16_kernel(const __half* __restrict__ qkv, __half* __restrict__ ctx)
{
    extern __shared__ __align__(16) __half sha[];
    __half* Qs = sha;
    __half* KV = sha + ATTN_Q_ELE;

    const int bh = blockIdx.x, qt = blockIdx.y;
    const int b = bh >> 4, h = bh & 15;
    const __half* base = qkv + (size_t)b * SS * NQKV + h * (3 * HDIM);

    const int tid = threadIdx.x;
    const int w = tid >> 5, lane = tid & 31;
    const int g = lane >> 2, tig = lane & 3;
    const int l16 = lane & 15;
    const int lhi = (lane >> 4) * 8;

    auto load_kv = [&](int kt, int st) {
        __half* Ks = KV + st * ATTN_STAGE_ELE;
        __half* Vs = Ks + ATTN_KV_ELE;
#pragma unroll
        for (int i = 0; i < 2; i++) {
            int l = tid + i * 256;
            int row = l >> 3, seg = l & 7;
            const __half* gp = base + (size_t)(kt * 64 + row) * NQKV + seg * 8;
            cpasync16(smem_u32(Ks + row * TS + seg * 8), gp + HDIM);
            cpasync16(smem_u32(Vs + row * TS + seg * 8), gp + 2 * HDIM);
        }
    };

#pragma unroll
    for (int i = 0; i < 4; i++) {
        int l = tid + i * 256;
        int row = l >> 3, seg = l & 7;
        cpasync16(smem_u32(Qs + row * TS + seg * 8),
                  base + (size_t)(qt * 128 + row) * NQKV + seg * 8);
    }
    load_kv(0, 0); CP_COMMIT();
    load_kv(1, 1); CP_COMMIT();
    load_kv(2, 2); CP_COMMIT();

    uint32_t qf[4][4];
    float o[8][4];
#pragma unroll
    for (int ni = 0; ni < 8; ni++)
#pragma unroll
        for (int q = 0; q < 4; q++) o[ni][q] = 0.0f;
    float m_lo = -1e30f, m_hi = -1e30f, l_lo = 0.0f, l_hi = 0.0f;

    for (int kt = 0; kt < 32; kt++) {
        if (kt <= 29)      { CP_WAIT2(); }
        else if (kt == 30) { CP_WAIT1(); }
        else               { CP_WAIT0(); }
        __syncthreads();

        if (kt + 3 < 32) { load_kv(kt + 3, (kt + 3) & 3); CP_COMMIT(); }

        if (kt == 0) {
#pragma unroll
            for (int kc = 0; kc < 4; kc++)
                ldmatrix_x4(qf[kc], smem_u32(Qs + (w * 16 + l16) * TS + kc * 16 + lhi));
        }

        const int st = kt & 3;
        const __half* Kb = KV + st * ATTN_STAGE_ELE;
        const __half* Vb = Kb + ATTN_KV_ELE;

        float sfr[8][4];
#pragma unroll
        for (int ni = 0; ni < 8; ni++)
#pragma unroll
            for (int q = 0; q < 4; q++) sfr[ni][q] = 0.0f;
#pragma unroll
        for (int kc = 0; kc < 4; kc++) {
#pragma unroll
            for (int p = 0; p < 4; p++) {
                uint32_t t4[4];
                uint32_t addr = smem_u32(Kb + (p * 16 + ((lane >> 4) << 3) + (lane & 7)) * TS
                                         + kc * 16 + (((lane >> 3) & 1) << 3));
                ldmatrix_x4(t4, addr);
                mma_f16_f32(sfr[2 * p],     qf[kc], &t4[0]);
                mma_f16_f32(sfr[2 * p + 1], qf[kc], &t4[2]);
            }
        }

        float tl = -1e30f, th = -1e30f;
#pragma unroll
        for (int ni = 0; ni < 8; ni++) {
            tl = fmaxf(tl, fmaxf(sfr[ni][0], sfr[ni][1]));
            th = fmaxf(th, fmaxf(sfr[ni][2], sfr[ni][3]));
        }
        tl = fmaxf(tl, __shfl_xor_sync(0xffffffffu, tl, 1));
        tl = fmaxf(tl, __shfl_xor_sync(0xffffffffu, tl, 2));
        th = fmaxf(th, __shfl_xor_sync(0xffffffffu, th, 1));
        th = fmaxf(th, __shfl_xor_sync(0xffffffffu, th, 2));

        float mnl = fmaxf(m_lo, tl), mnh = fmaxf(m_hi, th);
        float al = __expf(m_lo - mnl), ah = __expf(m_hi - mnh);
        m_lo = mnl; m_hi = mnh;

        float sl = 0.0f, shi = 0.0f;
#pragma unroll
        for (int ni = 0; ni < 8; ni++) {
            sfr[ni][0] = __expf(sfr[ni][0] - m_lo);
            sfr[ni][1] = __expf(sfr[ni][1] - m_lo);
            sfr[ni][2] = __expf(sfr[ni][2] - m_hi);
            sfr[ni][3] = __expf(sfr[ni][3] - m_hi);
            sl  += sfr[ni][0] + sfr[ni][1];
            shi += sfr[ni][2] + sfr[ni][3];
        }
        l_lo = l_lo * al + sl;
        l_hi = l_hi * ah + shi;
#pragma unroll
        for (int ni = 0; ni < 8; ni++) {
            o[ni][0] *= al; o[ni][1] *= al;
            o[ni][2] *= ah; o[ni][3] *= ah;
        }

        uint32_t pu[4][4];
#pragma unroll
        for (int j = 0; j < 4; j++) {
            pu[j][0] = pack_f16(sfr[2 * j][0],     sfr[2 * j][1]);
            pu[j][1] = pack_f16(sfr[2 * j][2],     sfr[2 * j][3]);
            pu[j][2] = pack_f16(sfr[2 * j + 1][0], sfr[2 * j + 1][1]);
            pu[j][3] = pack_f16(sfr[2 * j + 1][2], sfr[2 * j + 1][3]);
        }

#pragma unroll
        for (int kc = 0; kc < 4; kc++) {
#pragma unroll
            for (int p = 0; p < 4; p++) {
                uint32_t t4[4];
                ldmatrix_x4t(t4, smem_u32(Vb + (kc * 16 + l16) * TS + p * 16 + lhi));
                mma_f16_f32(o[2 * p],     pu[kc], &t4[0]);
                mma_f16_f32(o[2 * p + 1], pu[kc], &t4[2]);
            }
        }
    }

    l_lo += __shfl_xor_sync(0xffffffffu, l_lo, 1);
    l_lo += __shfl_xor_sync(0xffffffffu, l_lo, 2);
    l_hi += __shfl_xor_sync(0xffffffffu, l_hi, 1);
    l_hi += __shfl_xor_sync(0xffffffffu, l_hi, 2);
    const float il = 1.0f / l_lo, ih = 1.0f / l_hi;

    const int row0 = b * SS + qt * 128 + w * 16 + g;
#pragma unroll
    for (int ni = 0; ni < 8; ni++) {
        const int col = h * HDIM + ni * 8 + 2 * tig;
        *(uint32_t*)(ctx + (size_t)row0 * HH + col) =
            pack_f16(o[ni][0] * il, o[ni][1] * il);
        *(uint32_t*)(ctx + (size_t)(row0 + 8) * HH + col) =
            pack_f16(o[ni][2] * ih, o[ni][3] * ih);
    }
}

// ============================================================================
// LayerNorm: one warp per row (R10-proven)
// ============================================================================
__global__ __launch_bounds__(256)
void layernorm_warp_kernel(const float* __restrict__ x, const float* __restrict__ gamma,
                           const float* __restrict__ beta, float* __restrict__ out)
{
    const int w = threadIdx.x >> 5;
    const int lane = threadIdx.x & 31;
    const int row = blockIdx.x * 8 + w;

    const float4* xp = (const float4*)(x + (size_t)row * HH);
    float4 v[8];
    float s = 0.0f, s2 = 0.0f;
#pragma unroll
    for (int i = 0; i < 8; i++) {
        v[i] = xp[lane + i * 32];
        s  += v[i].x + v[i].y + v[i].z + v[i].w;
        s2 += v[i].x * v[i].x + v[i].y * v[i].y + v[i].z * v[i].z + v[i].w * v[i].w;
    }
#pragma unroll
    for (int o = 16; o > 0; o >>= 1) {
        s  += __shfl_xor_sync(~0u, s, o);
        s2 += __shfl_xor_sync(~0u, s2, o);
    }
    const float mu = s * (1.0f / HH);
    const float var = s2 * (1.0f / HH) - mu * mu;
    const float rstd = rsqrtf(var + 1e-5f);

    const float4* gp = (const float4*)gamma;
    const float4* bp = (const float4*)beta;
    float4* op = (float4*)(out + (size_t)row * HH);
#pragma unroll
    for (int i = 0; i < 8; i++) {
        const float4 gm = gp[lane + i * 32];
        const float4 bt = bp[lane + i * 32];
        float4 o;
        o.x = (v[i].x - mu) * rstd * gm.x + bt.x;
        o.y = (v[i].y - mu) * rstd * gm.y + bt.y;
        o.z = (v[i].z - mu) * rstd * gm.z + bt.z;
        o.w = (v[i].w - mu) * rstd * gm.w + bt.w;
        op[lane + i * 32] = o;
    }
}

// ============================================================================
extern "C" void kernel_launch(void* const* d_in, const int* in_sizes, int n_in,
                              void* d_out, int out_size)
{
    const float* hidden  = (const float*)d_in[0];
    const float* w_qkv   = (const float*)d_in[1];
    const float* b_qkv   = (const float*)d_in[2];
    const float* w_dense = (const float*)d_in[3];
    const float* b_dense = (const float*)d_in[4];
    const float* gamma   = (const float*)d_in[5];
    const float* beta    = (const float*)d_in[6];
    float* out = (float*)d_out;

    __half *hid, *wq, *wd, *qkv, *ctx;
    float* x;
    cudaGetSymbolAddress((void**)&hid, g_hid_h);
    cudaGetSymbolAddress((void**)&wq,  g_wq_h);
    cudaGetSymbolAddress((void**)&wd,  g_wd_h);
    cudaGetSymbolAddress((void**)&qkv, g_qkv_h);
    cudaGetSymbolAddress((void**)&ctx, g_ctx_h);
    cudaGetSymbolAddress((void**)&x,   g_x);

    // 0) all fp32 -> fp16 conversions, one launch, 4 float4/thread
    f2h_all_kernel<<<2048, 256>>>(hidden, w_qkv, w_dense, hid, wq, wd);

    // 1) QKV projection (128x256 tile, 4-stage ring) -> fp16, Q pre-scaled 1/8
    cudaFuncSetAttribute(gemm_qkv_kernel,
                         cudaFuncAttributeMaxDynamicSharedMemorySize, QKV_SMEM_BYTES);
    gemm_qkv_kernel<<<dim3(NQKV / 256, MTOT / 128), 256, QKV_SMEM_BYTES>>>(
        hid, wq, b_qkv, qkv, HH, NQKV);

    // 2) Flash attention
    cudaFuncSetAttribute(attn_f16_kernel,
                         cudaFuncAttributeMaxDynamicSharedMemorySize, ATTN_SMEM_BYTES);
    attn_f16_kernel<<<dim3(32, 16), 256, ATTN_SMEM_BYTES>>>(qkv, ctx);

    // 3) Dense projection (128x128 tile, 4 warps of 64x64, 4-stage ring)
    cudaFuncSetAttribute(gemm_dense_kernel,
                         cudaFuncAttributeMaxDynamicSharedMemorySize, DENSE_SMEM_BYTES);
    gemm_dense_kernel<<<dim3(HH / 128, MTOT / 128), 128, DENSE_SMEM_BYTES>>>(
        ctx, wd, b_dense, hidden, x, HH, HH);

    // 4) LayerNorm (one warp per row)
    layernorm_warp_kernel<<<MTOT / 8, 256>>>(x, gamma, beta, out);
}

// round 14
// speedup vs baseline: 1.0756x; 1.0756x over previous
#include <cuda_runtime.h>
#include <cuda_fp16.h>
#include <cstdint>
#include <math.h>

#define BB 2
#define SS 2048
#define HH 1024
#define NHEADS 16
#define HDIM 64
#define MTOT (BB*SS)      // 4096
#define NQKV (3*HH)       // 3072

// Scratch (allocation-free rule: __device__ globals)
__device__ __half g_hid_h[(size_t)MTOT * HH];    // 8 MiB
__device__ __half g_wq_h[(size_t)HH * NQKV];     // 6 MiB
__device__ __half g_wd_h[(size_t)HH * HH];       // 2 MiB
__device__ __half g_qkv_h[(size_t)MTOT * NQKV];  // 24 MiB (Q pre-scaled 1/8)
__device__ __half g_ctx_h[(size_t)MTOT * HH];    // 8 MiB
__device__ float g_x[(size_t)MTOT * HH];         // 16 MiB

// ============================================================================
// helpers
// ============================================================================
__device__ __forceinline__ uint32_t smem_u32(const void* p) {
    uint32_t a;
    asm("{ .reg .u64 t; cvta.to.shared.u64 t, %1; cvt.u32.u64 %0, t; }"
        : "=r"(a) : "l"(p));
    return a;
}
__device__ __forceinline__ void cpasync16(uint32_t s, const void* g) {
    asm volatile("cp.async.cg.shared.global [%0], [%1], 16;" :: "r"(s), "l"(g));
}
#define CP_COMMIT() asm volatile("cp.async.commit_group;" ::: "memory")
#define CP_WAIT0()  asm volatile("cp.async.wait_group 0;" ::: "memory")
#define CP_WAIT1()  asm volatile("cp.async.wait_group 1;" ::: "memory")
#define CP_WAIT2()  asm volatile("cp.async.wait_group 2;" ::: "memory")

// pack two f32 -> f16x2 (lo = first arg, hi = second arg)
__device__ __forceinline__ uint32_t pack_f16(float lo, float hi) {
    uint32_t r;
    asm("cvt.rn.f16x2.f32 %0, %1, %2;" : "=r"(r) : "f"(hi), "f"(lo));
    return r;
}
// fp16 m16n8k16, fp32 accumulate (all GEMMs + attention)
__device__ __forceinline__ void mma_f16_f32(float c[4], const uint32_t a[4],
                                            const uint32_t b[2]) {
    asm volatile(
        "mma.sync.aligned.m16n8k16.row.col.f32.f16.f16.f32 "
        "{%0,%1,%2,%3}, {%4,%5,%6,%7}, {%8,%9}, {%0,%1,%2,%3};\n"
        : "+f"(c[0]), "+f"(c[1]), "+f"(c[2]), "+f"(c[3])
        : "r"(a[0]), "r"(a[1]), "r"(a[2]), "r"(a[3]), "r"(b[0]), "r"(b[1]));
}
__device__ __forceinline__ void ldmatrix_x4(uint32_t r[4], uint32_t addr) {
    asm volatile("ldmatrix.sync.aligned.m8n8.x4.shared.b16 {%0,%1,%2,%3}, [%4];"
                 : "=r"(r[0]), "=r"(r[1]), "=r"(r[2]), "=r"(r[3]) : "r"(addr));
}
__device__ __forceinline__ void ldmatrix_x4t(uint32_t r[4], uint32_t addr) {
    asm volatile("ldmatrix.sync.aligned.m8n8.x4.trans.shared.b16 {%0,%1,%2,%3}, [%4];"
                 : "=r"(r[0]), "=r"(r[1]), "=r"(r[2]), "=r"(r[3]) : "r"(addr));
}

// ============================================================================
// prep: single-launch fp32 -> fp16 convert, 4 float4 per thread (MLP=4)
// blocks [0,1024): hidden, [1024,1792): w_qkv, [1792,2048): w_dense
// ============================================================================
__global__ __launch_bounds__(256)
void f2h_all_kernel(const float* __restrict__ hid_f, const float* __restrict__ wq_f,
                    const float* __restrict__ wd_f, __half* __restrict__ hid_h,
                    __half* __restrict__ wq_h, __half* __restrict__ wd_h)
{
    const int b = blockIdx.x;
    const float* in;
    __half* out;
    int rb;
    if (b < 1024)      { in = hid_f; out = hid_h; rb = b; }
    else if (b < 1792) { in = wq_f;  out = wq_h;  rb = b - 1024; }
    else               { in = wd_f;  out = wd_h;  rb = b - 1792; }

    float4 v[4];
#pragma unroll
    for (int i = 0; i < 4; i++)
        v[i] = ((const float4*)in)[(size_t)rb * 1024 + i * 256 + threadIdx.x];
#pragma unroll
    for (int i = 0; i < 4; i++) {
        uint2 o;
        o.x = pack_f16(v[i].x, v[i].y);
        o.y = pack_f16(v[i].z, v[i].w);
        ((uint2*)out)[(size_t)rb * 1024 + i * 256 + threadIdx.x] = o;
    }
}

// ============================================================================
// GEMM (R11 config, race-fixed): 128x256 CTA tile, BK=64, 256 threads
// (8 warps as 2x4 of 64x64), 3-stage cp.async ring with prefetch AFTER the
// compute loop, guarded by an extra __syncthreads() so the overwritten slot
// (ks%3) is provably no longer being read by any warp.
// QKV variant: out fp16, +bias, Q cols (c%192<64) scaled by 0.125.
// Dense variant: out fp32, +bias, +residual.
// ============================================================================
#define AS_STR 72
#define BS_STR 264
#define AS_ELE (128 * AS_STR)
#define BS_ELE (64 * BS_STR)
#define STAGE_ELE (AS_ELE + BS_ELE)            // 26112
#define GEMM_SMEM_BYTES (3 * STAGE_ELE * 2)    // 156672

template<bool QKV>
__global__ __launch_bounds__(256)
void gemm_f16_kernel(const __half* __restrict__ A, const __half* __restrict__ B,
                     const float* __restrict__ bias, const float* __restrict__ res,
                     void* __restrict__ Cout, int K, int N)
{
    extern __shared__ __align__(16) __half sh[];

    const int tid = threadIdx.x;
    const int w = tid >> 5, lane = tid & 31;
    const int g = lane >> 2, tig = lane & 3;
    const int wm = w >> 2;          // 0..1 : 64-row slab
    const int wn = w & 3;           // 0..3 : 64-col slab
    const int bm = blockIdx.y * 128, bn = blockIdx.x * 256;
    const int nst = K / 64;

    float cf[4][8][4];
#pragma unroll
    for (int mi = 0; mi < 4; mi++)
#pragma unroll
        for (int ni = 0; ni < 8; ni++)
#pragma unroll
            for (int q = 0; q < 4; q++) cf[mi][ni][q] = 0.0f;

    auto load_stage = [&](int st, int ks) {
        __half* As = sh + st * STAGE_ELE;
        __half* Bs = As + AS_ELE;
#pragma unroll
        for (int i = 0; i < 4; i++) {
            int l = tid + i * 256;
            int row = l >> 3, seg = l & 7;
            cpasync16(smem_u32(As + row * AS_STR + seg * 8),
                      A + (size_t)(bm + row) * K + ks * 64 + seg * 8);
        }
#pragma unroll
        for (int i = 0; i < 8; i++) {
            int l = tid + i * 256;
            int row = l >> 5, seg = l & 31;
            cpasync16(smem_u32(Bs + row * BS_STR + seg * 8),
                      B + (size_t)(ks * 64 + row) * N + bn + seg * 8);
        }
    };

    load_stage(0, 0); CP_COMMIT();
    load_stage(1, 1); CP_COMMIT();
    load_stage(2, 2); CP_COMMIT();

    const int l16 = lane & 15;
    const int lhi = (lane >> 4) * 8;

    for (int ks = 0; ks < nst; ks++) {
        if (ks <= nst - 3)      { CP_WAIT2(); }
        else if (ks == nst - 2) { CP_WAIT1(); }
        else                    { CP_WAIT0(); }
        __syncthreads();

        const int st = ks % 3;
        const __half* Ab = sh + st * STAGE_ELE;
        const __half* Bb = Ab + AS_ELE;
#pragma unroll
        for (int kc = 0; kc < 4; kc++) {
            uint32_t au[4][4];
#pragma unroll
            for (int mi = 0; mi < 4; mi++)
                ldmatrix_x4(au[mi], smem_u32(Ab + (wm * 64 + mi * 16 + l16) * AS_STR
                                             + kc * 16 + lhi));
            uint32_t bu[8][2];
#pragma unroll
            for (int p = 0; p < 4; p++) {
                uint32_t t4[4];
                ldmatrix_x4t(t4, smem_u32(Bb + (kc * 16 + l16) * BS_STR
                                          + wn * 64 + p * 16 + lhi));
                bu[2 * p][0] = t4[0]; bu[2 * p][1] = t4[1];
                bu[2 * p + 1][0] = t4[2]; bu[2 * p + 1][1] = t4[3];
            }
#pragma unroll
            for (int mi = 0; mi < 4; mi++)
#pragma unroll
                for (int ni = 0; ni < 8; ni++)
                    mma_f16_f32(cf[mi][ni], au[mi], bu[ni]);
        }

        if (ks + 3 < nst) {
            // RACE FIX: slot (ks+3)%3 == ks%3 is the buffer just computed on.
            // Barrier ensures every warp finished its ldmatrix reads before
            // any thread overwrites it.
            __syncthreads();
            load_stage((ks + 3) % 3, ks + 3); CP_COMMIT();
        }
    }

    // epilogue
#pragma unroll
    for (int mi = 0; mi < 4; mi++) {
        const int r = bm + wm * 64 + mi * 16 + g;
#pragma unroll
        for (int ni = 0; ni < 8; ni++) {
            const int c = bn + wn * 64 + ni * 8 + 2 * tig;
            float v0 = cf[mi][ni][0] + bias[c];
            float v1 = cf[mi][ni][1] + bias[c + 1];
            float v2 = cf[mi][ni][2] + bias[c];
            float v3 = cf[mi][ni][3] + bias[c + 1];
            if (QKV) {
                if ((c % 192) < 64) { v0 *= 0.125f; v1 *= 0.125f; v2 *= 0.125f; v3 *= 0.125f; }
                __half* Ch = (__half*)Cout;
                *(uint32_t*)(Ch + (size_t)r * N + c) = pack_f16(v0, v1);
                *(uint32_t*)(Ch + (size_t)(r + 8) * N + c) = pack_f16(v2, v3);
            } else {
                float* Cf = (float*)Cout;
                const float2 r0 = *(const float2*)(res + (size_t)r * N + c);
                const float2 r1 = *(const float2*)(res + (size_t)(r + 8) * N + c);
                *(float2*)(Cf + (size_t)r * N + c) = make_float2(v0 + r0.x, v1 + r0.y);
                *(float2*)(Cf + (size_t)(r + 8) * N + c) = make_float2(v2 + r1.x, v3 + r1.y);
            }
        }
    }
}

// ============================================================================
// Flash attention (R10/R11-proven, byte-identical — race-free 4-stage ring)
// ============================================================================
#define TS 72
#define ATTN_Q_ELE (128 * TS)
#define ATTN_KV_ELE (64 * TS)
#define ATTN_STAGE_ELE (2 * ATTN_KV_ELE)
#define ATTN_SMEM_BYTES ((ATTN_Q_ELE + 4 * ATTN_STAGE_ELE) * 2)  // 92160

__global__ __launch_bounds__(256)
void attn_f16_kernel(const __half* __restrict__ qkv, __half* __restrict__ ctx)
{
    extern __shared__ __align__(16) __half sha[];
    __half* Qs = sha;
    __half* KV = sha + ATTN_Q_ELE;

    const int bh = blockIdx.x, qt = blockIdx.y;
    const int b = bh >> 4, h = bh & 15;
    const __half* base = qkv + (size_t)b * SS * NQKV + h * (3 * HDIM);

    const int tid = threadIdx.x;
    const int w = tid >> 5, lane = tid & 31;
    const int g = lane >> 2, tig = lane & 3;
    const int l16 = lane & 15;
    const int lhi = (lane >> 4) * 8;

    auto load_kv = [&](int kt, int st) {
        __half* Ks = KV + st * ATTN_STAGE_ELE;
        __half* Vs = Ks + ATTN_KV_ELE;
#pragma unroll
        for (int i = 0; i < 2; i++) {
            int l = tid + i * 256;
            int row = l >> 3, seg = l & 7;
            const __half* gp = base + (size_t)(kt * 64 + row) * NQKV + seg * 8;
            cpasync16(smem_u32(Ks + row * TS + seg * 8), gp + HDIM);
            cpasync16(smem_u32(Vs + row * TS + seg * 8), gp + 2 * HDIM);
        }
    };

#pragma unroll
    for (int i = 0; i < 4; i++) {
        int l = tid + i * 256;
        int row = l >> 3, seg = l & 7;
        cpasync16(smem_u32(Qs + row * TS + seg * 8),
                  base + (size_t)(qt * 128 + row) * NQKV + seg * 8);
    }
    load_kv(0, 0); CP_COMMIT();
    load_kv(1, 1); CP_COMMIT();
    load_kv(2, 2); CP_COMMIT();

    uint32_t qf[4][4];
    float o[8][4];
#pragma unroll
    for (int ni = 0; ni < 8; ni++)
#pragma unroll
        for (int q = 0; q < 4; q++) o[ni][q] = 0.0f;
    float m_lo = -1e30f, m_hi = -1e30f, l_lo = 0.0f, l_hi = 0.0f;

    for (int kt = 0; kt < 32; kt++) {
        if (kt <= 29)      { CP_WAIT2(); }
        else if (kt == 30) { CP_WAIT1(); }
        else               { CP_WAIT0(); }
        __syncthreads();

        if (kt == 0) {
#pragma unroll
            for (int kc = 0; kc < 4; kc++)
                ldmatrix_x4(qf[kc], smem_u32(Qs + (w * 16 + l16) * TS + kc * 16 + lhi));
        }

        const int st = kt & 3;
        const __half* Kb = KV + st * ATTN_STAGE_ELE;
        const __half* Vb = Kb + ATTN_KV_ELE;

        float sfr[8][4];
#pragma unroll
        for (int ni = 0; ni < 8; ni++)
#pragma unroll
            for (int q = 0; q < 4; q++) sfr[ni][q] = 0.0f;
#pragma unroll
        for (int kc = 0; kc < 4; kc++) {
#pragma unroll
            for (int p = 0; p < 4; p++) {
                uint32_t t4[4];
                uint32_t addr = smem_u32(Kb + (p * 16 + ((lane >> 4) << 3) + (lane & 7)) * TS
                                         + kc * 16 + (((lane >> 3) & 1) << 3));
                ldmatrix_x4(t4, addr);
                mma_f16_f32(sfr[2 * p],     qf[kc], &t4[0]);
                mma_f16_f32(sfr[2 * p + 1], qf[kc], &t4[2]);
            }
        }

        float tl = -1e30f, th = -1e30f;
#pragma unroll
        for (int ni = 0; ni < 8; ni++) {
            tl = fmaxf(tl, fmaxf(sfr[ni][0], sfr[ni][1]));
            th = fmaxf(th, fmaxf(sfr[ni][2], sfr[ni][3]));
        }
        tl = fmaxf(tl, __shfl_xor_sync(0xffffffffu, tl, 1));
        tl = fmaxf(tl, __shfl_xor_sync(0xffffffffu, tl, 2));
        th = fmaxf(th, __shfl_xor_sync(0xffffffffu, th, 1));
        th = fmaxf(th, __shfl_xor_sync(0xffffffffu, th, 2));

        float mnl = fmaxf(m_lo, tl), mnh = fmaxf(m_hi, th);
        float al = __expf(m_lo - mnl), ah = __expf(m_hi - mnh);
        m_lo = mnl; m_hi = mnh;

        float sl = 0.0f, shi = 0.0f;
#pragma unroll
        for (int ni = 0; ni < 8; ni++) {
            sfr[ni][0] = __expf(sfr[ni][0] - m_lo);
            sfr[ni][1] = __expf(sfr[ni][1] - m_lo);
            sfr[ni][2] = __expf(sfr[ni][2] - m_hi);
            sfr[ni][3] = __expf(sfr[ni][3] - m_hi);
            sl  += sfr[ni][0] + sfr[ni][1];
            shi += sfr[ni][2] + sfr[ni][3];
        }
        l_lo = l_lo * al + sl;
        l_hi = l_hi * ah + shi;
#pragma unroll
        for (int ni = 0; ni < 8; ni++) {
            o[ni][0] *= al; o[ni][1] *= al;
            o[ni][2] *= ah; o[ni][3] *= ah;
        }

        uint32_t pu[4][4];
#pragma unroll
        for (int j = 0; j < 4; j++) {
            pu[j][0] = pack_f16(sfr[2 * j][0],     sfr[2 * j][1]);
            pu[j][1] = pack_f16(sfr[2 * j][2],     sfr[2 * j][3]);
            pu[j][2] = pack_f16(sfr[2 * j + 1][0], sfr[2 * j + 1][1]);
            pu[j][3] = pack_f16(sfr[2 * j + 1][2], sfr[2 * j + 1][3]);
        }

#pragma unroll
        for (int kc = 0; kc < 4; kc++) {
#pragma unroll
            for (int p = 0; p < 4; p++) {
                uint32_t t4[4];
                ldmatrix_x4t(t4, smem_u32(Vb + (kc * 16 + l16) * TS + p * 16 + lhi));
                mma_f16_f32(o[2 * p],     pu[kc], &t4[0]);
                mma_f16_f32(o[2 * p + 1], pu[kc], &t4[2]);
            }
        }

        if (kt + 3 < 32) { load_kv(kt + 3, (kt + 3) & 3); CP_COMMIT(); }
    }

    l_lo += __shfl_xor_sync(0xffffffffu, l_lo, 1);
    l_lo += __shfl_xor_sync(0xffffffffu, l_lo, 2);
    l_hi += __shfl_xor_sync(0xffffffffu, l_hi, 1);
    l_hi += __shfl_xor_sync(0xffffffffu, l_hi, 2);
    const float il = 1.0f / l_lo, ih = 1.0f / l_hi;

    const int row0 = b * SS + qt * 128 + w * 16 + g;
#pragma unroll
    for (int ni = 0; ni < 8; ni++) {
        const int col = h * HDIM + ni * 8 + 2 * tig;
        *(uint32_t*)(ctx + (size_t)row0 * HH + col) =
            pack_f16(o[ni][0] * il, o[ni][1] * il);
        *(uint32_t*)(ctx + (size_t)(row0 + 8) * HH + col) =
            pack_f16(o[ni][2] * ih, o[ni][3] * ih);
    }
}

// ============================================================================
// LayerNorm: one warp per row (R10-proven)
// ============================================================================
__global__ __launch_bounds__(256)
void layernorm_warp_kernel(const float* __restrict__ x, const float* __restrict__ gamma,
                           const float* __restrict__ beta, float* __restrict__ out)
{
    const int w = threadIdx.x >> 5;
    const int lane = threadIdx.x & 31;
    const int row = blockIdx.x * 8 + w;

    const float4* xp = (const float4*)(x + (size_t)row * HH);
    float4 v[8];
    float s = 0.0f, s2 = 0.0f;
#pragma unroll
    for (int i = 0; i < 8; i++) {
        v[i] = xp[lane + i * 32];
        s  += v[i].x + v[i].y + v[i].z + v[i].w;
        s2 += v[i].x * v[i].x + v[i].y * v[i].y + v[i].z * v[i].z + v[i].w * v[i].w;
    }
#pragma unroll
    for (int o = 16; o > 0; o >>= 1) {
        s  += __shfl_xor_sync(~0u, s, o);
        s2 += __shfl_xor_sync(~0u, s2, o);
    }
    const float mu = s * (1.0f / HH);
    const float var = s2 * (1.0f / HH) - mu * mu;
    const float rstd = rsqrtf(var + 1e-5f);

    const float4* gp = (const float4*)gamma;
    const float4* bp = (const float4*)beta;
    float4* op = (float4*)(out + (size_t)row * HH);
#pragma unroll
    for (int i = 0; i < 8; i++) {
        const float4 gm = gp[lane + i * 32];
        const float4 bt = bp[lane + i * 32];
        float4 o;
        o.x = (v[i].x - mu) * rstd * gm.x + bt.x;
        o.y = (v[i].y - mu) * rstd * gm.y + bt.y;
        o.z = (v[i].z - mu) * rstd * gm.z + bt.z;
        o.w = (v[i].w - mu) * rstd * gm.w + bt.w;
        op[lane + i * 32] = o;
    }
}

// ============================================================================
extern "C" void kernel_launch(void* const* d_in, const int* in_sizes, int n_in,
                              void* d_out, int out_size)
{
    const float* hidden  = (const float*)d_in[0];
    const float* w_qkv   = (const float*)d_in[1];
    const float* b_qkv   = (const float*)d_in[2];
    const float* w_dense = (const float*)d_in[3];
    const float* b_dense = (const float*)d_in[4];
    const float* gamma   = (const float*)d_in[5];
    const float* beta    = (const float*)d_in[6];
    float* out = (float*)d_out;

    __half *hid, *wq, *wd, *qkv, *ctx;
    float* x;
    cudaGetSymbolAddress((void**)&hid, g_hid_h);
    cudaGetSymbolAddress((void**)&wq,  g_wq_h);
    cudaGetSymbolAddress((void**)&wd,  g_wd_h);
    cudaGetSymbolAddress((void**)&qkv, g_qkv_h);
    cudaGetSymbolAddress((void**)&ctx, g_ctx_h);
    cudaGetSymbolAddress((void**)&x,   g_x);

    // 0) all fp32 -> fp16 conversions, one launch, 4 float4/thread
    f2h_all_kernel<<<2048, 256>>>(hidden, w_qkv, w_dense, hid, wq, wd);

    // 1) QKV projection (128x256 tile, race-fixed 3-stage) -> fp16, Q/8
    cudaFuncSetAttribute(gemm_f16_kernel<true>,
                         cudaFuncAttributeMaxDynamicSharedMemorySize, GEMM_SMEM_BYTES);
    gemm_f16_kernel<true><<<dim3(NQKV / 256, MTOT / 128), 256, GEMM_SMEM_BYTES>>>(
        hid, wq, b_qkv, nullptr, qkv, HH, NQKV);

    // 2) Flash attention
    cudaFuncSetAttribute(attn_f16_kernel,
                         cudaFuncAttributeMaxDynamicSharedMemorySize, ATTN_SMEM_BYTES);
    attn_f16_kernel<<<dim3(32, 16), 256, ATTN_SMEM_BYTES>>>(qkv, ctx);

    // 3) Dense projection (128x256 tile, race-fixed 3-stage) + bias + residual
    cudaFuncSetAttribute(gemm_f16_kernel<false>,
                         cudaFuncAttributeMaxDynamicSharedMemorySize, GEMM_SMEM_BYTES);
    gemm_f16_kernel<false><<<dim3(HH / 256, MTOT / 128), 256, GEMM_SMEM_BYTES>>>(
        ctx, wd, b_dense, hidden, x, HH, HH);

    // 4) LayerNorm (one warp per row)
    layernorm_warp_kernel<<<MTOT / 8, 256>>>(x, gamma, beta, out);
}

// round 15
// speedup vs baseline: 1.0992x; 1.0220x over previous
#include <cuda_runtime.h>
#include <cuda_fp16.h>
#include <cstdint>
#include <math.h>

#define BB 2
#define SS 2048
#define HH 1024
#define NHEADS 16
#define HDIM 64
#define MTOT (BB*SS)      // 4096
#define NQKV (3*HH)       // 3072

// Scratch (allocation-free rule: __device__ globals)
__device__ __half g_hid_h[(size_t)MTOT * HH];    // 8 MiB
__device__ __half g_wq_h[(size_t)HH * NQKV];     // 6 MiB
__device__ __half g_wd_h[(size_t)HH * HH];       // 2 MiB
__device__ __half g_qkv_h[(size_t)MTOT * NQKV];  // 24 MiB (Q pre-scaled 1/8)
__device__ __half g_ctx_h[(size_t)MTOT * HH];    // 8 MiB
__device__ float g_x[(size_t)MTOT * HH];         // 16 MiB

// ============================================================================
// helpers
// ============================================================================
__device__ __forceinline__ uint32_t smem_u32(const void* p) {
    uint32_t a;
    asm("{ .reg .u64 t; cvta.to.shared.u64 t, %1; cvt.u32.u64 %0, t; }"
        : "=r"(a) : "l"(p));
    return a;
}
__device__ __forceinline__ void cpasync16(uint32_t s, const void* g) {
    asm volatile("cp.async.cg.shared.global [%0], [%1], 16;" :: "r"(s), "l"(g));
}
#define CP_COMMIT() asm volatile("cp.async.commit_group;" ::: "memory")
#define CP_WAIT0()  asm volatile("cp.async.wait_group 0;" ::: "memory")
#define CP_WAIT1()  asm volatile("cp.async.wait_group 1;" ::: "memory")
#define CP_WAIT2()  asm volatile("cp.async.wait_group 2;" ::: "memory")

// pack two f32 -> f16x2 (lo = first arg, hi = second arg)
__device__ __forceinline__ uint32_t pack_f16(float lo, float hi) {
    uint32_t r;
    asm("cvt.rn.f16x2.f32 %0, %1, %2;" : "=r"(r) : "f"(hi), "f"(lo));
    return r;
}
// fp16 m16n8k16, fp32 accumulate (all GEMMs + attention)
__device__ __forceinline__ void mma_f16_f32(float c[4], const uint32_t a[4],
                                            const uint32_t b[2]) {
    asm volatile(
        "mma.sync.aligned.m16n8k16.row.col.f32.f16.f16.f32 "
        "{%0,%1,%2,%3}, {%4,%5,%6,%7}, {%8,%9}, {%0,%1,%2,%3};\n"
        : "+f"(c[0]), "+f"(c[1]), "+f"(c[2]), "+f"(c[3])
        : "r"(a[0]), "r"(a[1]), "r"(a[2]), "r"(a[3]), "r"(b[0]), "r"(b[1]));
}
__device__ __forceinline__ void ldmatrix_x4(uint32_t r[4], uint32_t addr) {
    asm volatile("ldmatrix.sync.aligned.m8n8.x4.shared.b16 {%0,%1,%2,%3}, [%4];"
                 : "=r"(r[0]), "=r"(r[1]), "=r"(r[2]), "=r"(r[3]) : "r"(addr));
}
__device__ __forceinline__ void ldmatrix_x4t(uint32_t r[4], uint32_t addr) {
    asm volatile("ldmatrix.sync.aligned.m8n8.x4.trans.shared.b16 {%0,%1,%2,%3}, [%4];"
                 : "=r"(r[0]), "=r"(r[1]), "=r"(r[2]), "=r"(r[3]) : "r"(addr));
}

// ============================================================================
// prep: single-launch fp32 -> fp16 convert, 4 float4 per thread (MLP=4)
// blocks [0,1024): hidden, [1024,1792): w_qkv, [1792,2048): w_dense
// ============================================================================
__global__ __launch_bounds__(256)
void f2h_all_kernel(const float* __restrict__ hid_f, const float* __restrict__ wq_f,
                    const float* __restrict__ wd_f, __half* __restrict__ hid_h,
                    __half* __restrict__ wq_h, __half* __restrict__ wd_h)
{
    const int b = blockIdx.x;
    const float* in;
    __half* out;
    int rb;
    if (b < 1024)      { in = hid_f; out = hid_h; rb = b; }
    else if (b < 1792) { in = wq_f;  out = wq_h;  rb = b - 1024; }
    else               { in = wd_f;  out = wd_h;  rb = b - 1792; }

    float4 v[4];
#pragma unroll
    for (int i = 0; i < 4; i++)
        v[i] = ((const float4*)in)[(size_t)rb * 1024 + i * 256 + threadIdx.x];
#pragma unroll
    for (int i = 0; i < 4; i++) {
        uint2 o;
        o.x = pack_f16(v[i].x, v[i].y);
        o.y = pack_f16(v[i].z, v[i].w);
        ((uint2*)out)[(size_t)rb * 1024 + i * 256 + threadIdx.x] = o;
    }
}

// ============================================================================
// GEMM (R11 schedule, race-free): 128x256 CTA tile, BK=64, 256 threads
// (8 warps as 2x4 of 64x64), 4-STAGE cp.async ring with prefetch issued
// AFTER the compute loop. Safety: prefetch target (ks+3)&3 == (ks-1)&3 was
// last read in iteration ks-1; the single barrier at the top of iteration ks
// proves all warps finished those reads. One barrier per stage, R11 order.
// QKV variant: out fp16, +bias, Q cols (c%192<64) scaled by 0.125.
// Dense variant: out fp32, +bias, +residual.
// ============================================================================
#define AS_STR 72
#define BS_STR 264
#define AS_ELE (128 * AS_STR)
#define BS_ELE (64 * BS_STR)
#define STAGE_ELE (AS_ELE + BS_ELE)            // 26112
#define GEMM_SMEM_BYTES (4 * STAGE_ELE * 2)    // 208896

template<bool QKV>
__global__ __launch_bounds__(256)
void gemm_f16_kernel(const __half* __restrict__ A, const __half* __restrict__ B,
                     const float* __restrict__ bias, const float* __restrict__ res,
                     void* __restrict__ Cout, int K, int N)
{
    extern __shared__ __align__(16) __half sh[];

    const int tid = threadIdx.x;
    const int w = tid >> 5, lane = tid & 31;
    const int g = lane >> 2, tig = lane & 3;
    const int wm = w >> 2;          // 0..1 : 64-row slab
    const int wn = w & 3;           // 0..3 : 64-col slab
    const int bm = blockIdx.y * 128, bn = blockIdx.x * 256;
    const int nst = K / 64;

    float cf[4][8][4];
#pragma unroll
    for (int mi = 0; mi < 4; mi++)
#pragma unroll
        for (int ni = 0; ni < 8; ni++)
#pragma unroll
            for (int q = 0; q < 4; q++) cf[mi][ni][q] = 0.0f;

    auto load_stage = [&](int st, int ks) {
        __half* As = sh + st * STAGE_ELE;
        __half* Bs = As + AS_ELE;
#pragma unroll
        for (int i = 0; i < 4; i++) {
            int l = tid + i * 256;
            int row = l >> 3, seg = l & 7;
            cpasync16(smem_u32(As + row * AS_STR + seg * 8),
                      A + (size_t)(bm + row) * K + ks * 64 + seg * 8);
        }
#pragma unroll
        for (int i = 0; i < 8; i++) {
            int l = tid + i * 256;
            int row = l >> 5, seg = l & 31;
            cpasync16(smem_u32(Bs + row * BS_STR + seg * 8),
                      B + (size_t)(ks * 64 + row) * N + bn + seg * 8);
        }
    };

    load_stage(0, 0); CP_COMMIT();
    load_stage(1, 1); CP_COMMIT();
    load_stage(2, 2); CP_COMMIT();

    const int l16 = lane & 15;
    const int lhi = (lane >> 4) * 8;

    for (int ks = 0; ks < nst; ks++) {
        if (ks <= nst - 3)      { CP_WAIT2(); }
        else if (ks == nst - 2) { CP_WAIT1(); }
        else                    { CP_WAIT0(); }
        __syncthreads();

        const __half* Ab = sh + (ks & 3) * STAGE_ELE;
        const __half* Bb = Ab + AS_ELE;
#pragma unroll
        for (int kc = 0; kc < 4; kc++) {
            uint32_t au[4][4];
#pragma unroll
            for (int mi = 0; mi < 4; mi++)
                ldmatrix_x4(au[mi], smem_u32(Ab + (wm * 64 + mi * 16 + l16) * AS_STR
                                             + kc * 16 + lhi));
            uint32_t bu[8][2];
#pragma unroll
            for (int p = 0; p < 4; p++) {
                uint32_t t4[4];
                ldmatrix_x4t(t4, smem_u32(Bb + (kc * 16 + l16) * BS_STR
                                          + wn * 64 + p * 16 + lhi));
                bu[2 * p][0] = t4[0]; bu[2 * p][1] = t4[1];
                bu[2 * p + 1][0] = t4[2]; bu[2 * p + 1][1] = t4[3];
            }
#pragma unroll
            for (int mi = 0; mi < 4; mi++)
#pragma unroll
                for (int ni = 0; ni < 8; ni++)
                    mma_f16_f32(cf[mi][ni], au[mi], bu[ni]);
        }

        // prefetch AFTER compute (R11 order); slot (ks+3)&3 == (ks-1)&3 is
        // race-free: its last readers finished before this iteration's barrier
        if (ks + 3 < nst) { load_stage((ks + 3) & 3, ks + 3); CP_COMMIT(); }
    }

    // epilogue
#pragma unroll
    for (int mi = 0; mi < 4; mi++) {
        const int r = bm + wm * 64 + mi * 16 + g;
#pragma unroll
        for (int ni = 0; ni < 8; ni++) {
            const int c = bn + wn * 64 + ni * 8 + 2 * tig;
            float v0 = cf[mi][ni][0] + bias[c];
            float v1 = cf[mi][ni][1] + bias[c + 1];
            float v2 = cf[mi][ni][2] + bias[c];
            float v3 = cf[mi][ni][3] + bias[c + 1];
            if (QKV) {
                if ((c % 192) < 64) { v0 *= 0.125f; v1 *= 0.125f; v2 *= 0.125f; v3 *= 0.125f; }
                __half* Ch = (__half*)Cout;
                *(uint32_t*)(Ch + (size_t)r * N + c) = pack_f16(v0, v1);
                *(uint32_t*)(Ch + (size_t)(r + 8) * N + c) = pack_f16(v2, v3);
            } else {
                float* Cf = (float*)Cout;
                const float2 r0 = *(const float2*)(res + (size_t)r * N + c);
                const float2 r1 = *(const float2*)(res + (size_t)(r + 8) * N + c);
                *(float2*)(Cf + (size_t)r * N + c) = make_float2(v0 + r0.x, v1 + r0.y);
                *(float2*)(Cf + (size_t)(r + 8) * N + c) = make_float2(v2 + r1.x, v3 + r1.y);
            }
        }
    }
}

// ============================================================================
// Flash attention (R10/R11-proven, byte-identical — race-free 4-stage ring)
// ============================================================================
#define TS 72
#define ATTN_Q_ELE (128 * TS)
#define ATTN_KV_ELE (64 * TS)
#define ATTN_STAGE_ELE (2 * ATTN_KV_ELE)
#define ATTN_SMEM_BYTES ((ATTN_Q_ELE + 4 * ATTN_STAGE_ELE) * 2)  // 92160

__global__ __launch_bounds__(256)
void attn_f16_kernel(const __half* __restrict__ qkv, __half* __restrict__ ctx)
{
    extern __shared__ __align__(16) __half sha[];
    __half* Qs = sha;
    __half* KV = sha + ATTN_Q_ELE;

    const int bh = blockIdx.x, qt = blockIdx.y;
    const int b = bh >> 4, h = bh & 15;
    const __half* base = qkv + (size_t)b * SS * NQKV + h * (3 * HDIM);

    const int tid = threadIdx.x;
    const int w = tid >> 5, lane = tid & 31;
    const int g = lane >> 2, tig = lane & 3;
    const int l16 = lane & 15;
    const int lhi = (lane >> 4) * 8;

    auto load_kv = [&](int kt, int st) {
        __half* Ks = KV + st * ATTN_STAGE_ELE;
        __half* Vs = Ks + ATTN_KV_ELE;
#pragma unroll
        for (int i = 0; i < 2; i++) {
            int l = tid + i * 256;
            int row = l >> 3, seg = l & 7;
            const __half* gp = base + (size_t)(kt * 64 + row) * NQKV + seg * 8;
            cpasync16(smem_u32(Ks + row * TS + seg * 8), gp + HDIM);
            cpasync16(smem_u32(Vs + row * TS + seg * 8), gp + 2 * HDIM);
        }
    };

#pragma unroll
    for (int i = 0; i < 4; i++) {
        int l = tid + i * 256;
        int row = l >> 3, seg = l & 7;
        cpasync16(smem_u32(Qs + row * TS + seg * 8),
                  base + (size_t)(qt * 128 + row) * NQKV + seg * 8);
    }
    load_kv(0, 0); CP_COMMIT();
    load_kv(1, 1); CP_COMMIT();
    load_kv(2, 2); CP_COMMIT();

    uint32_t qf[4][4];
    float o[8][4];
#pragma unroll
    for (int ni = 0; ni < 8; ni++)
#pragma unroll
        for (int q = 0; q < 4; q++) o[ni][q] = 0.0f;
    float m_lo = -1e30f, m_hi = -1e30f, l_lo = 0.0f, l_hi = 0.0f;

    for (int kt = 0; kt < 32; kt++) {
        if (kt <= 29)      { CP_WAIT2(); }
        else if (kt == 30) { CP_WAIT1(); }
        else               { CP_WAIT0(); }
        __syncthreads();

        if (kt == 0) {
#pragma unroll
            for (int kc = 0; kc < 4; kc++)
                ldmatrix_x4(qf[kc], smem_u32(Qs + (w * 16 + l16) * TS + kc * 16 + lhi));
        }

        const int st = kt & 3;
        const __half* Kb = KV + st * ATTN_STAGE_ELE;
        const __half* Vb = Kb + ATTN_KV_ELE;

        float sfr[8][4];
#pragma unroll
        for (int ni = 0; ni < 8; ni++)
#pragma unroll
            for (int q = 0; q < 4; q++) sfr[ni][q] = 0.0f;
#pragma unroll
        for (int kc = 0; kc < 4; kc++) {
#pragma unroll
            for (int p = 0; p < 4; p++) {
                uint32_t t4[4];
                uint32_t addr = smem_u32(Kb + (p * 16 + ((lane >> 4) << 3) + (lane & 7)) * TS
                                         + kc * 16 + (((lane >> 3) & 1) << 3));
                ldmatrix_x4(t4, addr);
                mma_f16_f32(sfr[2 * p],     qf[kc], &t4[0]);
                mma_f16_f32(sfr[2 * p + 1], qf[kc], &t4[2]);
            }
        }

        float tl = -1e30f, th = -1e30f;
#pragma unroll
        for (int ni = 0; ni < 8; ni++) {
            tl = fmaxf(tl, fmaxf(sfr[ni][0], sfr[ni][1]));
            th = fmaxf(th, fmaxf(sfr[ni][2], sfr[ni][3]));
        }
        tl = fmaxf(tl, __shfl_xor_sync(0xffffffffu, tl, 1));
        tl = fmaxf(tl, __shfl_xor_sync(0xffffffffu, tl, 2));
        th = fmaxf(th, __shfl_xor_sync(0xffffffffu, th, 1));
        th = fmaxf(th, __shfl_xor_sync(0xffffffffu, th, 2));

        float mnl = fmaxf(m_lo, tl), mnh = fmaxf(m_hi, th);
        float al = __expf(m_lo - mnl), ah = __expf(m_hi - mnh);
        m_lo = mnl; m_hi = mnh;

        float sl = 0.0f, shi = 0.0f;
#pragma unroll
        for (int ni = 0; ni < 8; ni++) {
            sfr[ni][0] = __expf(sfr[ni][0] - m_lo);
            sfr[ni][1] = __expf(sfr[ni][1] - m_lo);
            sfr[ni][2] = __expf(sfr[ni][2] - m_hi);
            sfr[ni][3] = __expf(sfr[ni][3] - m_hi);
            sl  += sfr[ni][0] + sfr[ni][1];
            shi += sfr[ni][2] + sfr[ni][3];
        }
        l_lo = l_lo * al + sl;
        l_hi = l_hi * ah + shi;
#pragma unroll
        for (int ni = 0; ni < 8; ni++) {
            o[ni][0] *= al; o[ni][1] *= al;
            o[ni][2] *= ah; o[ni][3] *= ah;
        }

        uint32_t pu[4][4];
#pragma unroll
        for (int j = 0; j < 4; j++) {
            pu[j][0] = pack_f16(sfr[2 * j][0],     sfr[2 * j][1]);
            pu[j][1] = pack_f16(sfr[2 * j][2],     sfr[2 * j][3]);
            pu[j][2] = pack_f16(sfr[2 * j + 1][0], sfr[2 * j + 1][1]);
            pu[j][3] = pack_f16(sfr[2 * j + 1][2], sfr[2 * j + 1][3]);
        }

#pragma unroll
        for (int kc = 0; kc < 4; kc++) {
#pragma unroll
            for (int p = 0; p < 4; p++) {
                uint32_t t4[4];
                ldmatrix_x4t(t4, smem_u32(Vb + (kc * 16 + l16) * TS + p * 16 + lhi));
                mma_f16_f32(o[2 * p],     pu[kc], &t4[0]);
                mma_f16_f32(o[2 * p + 1], pu[kc], &t4[2]);
            }
        }

        if (kt + 3 < 32) { load_kv(kt + 3, (kt + 3) & 3); CP_COMMIT(); }
    }

    l_lo += __shfl_xor_sync(0xffffffffu, l_lo, 1);
    l_lo += __shfl_xor_sync(0xffffffffu, l_lo, 2);
    l_hi += __shfl_xor_sync(0xffffffffu, l_hi, 1);
    l_hi += __shfl_xor_sync(0xffffffffu, l_hi, 2);
    const float il = 1.0f / l_lo, ih = 1.0f / l_hi;

    const int row0 = b * SS + qt * 128 + w * 16 + g;
#pragma unroll
    for (int ni = 0; ni < 8; ni++) {
        const int col = h * HDIM + ni * 8 + 2 * tig;
        *(uint32_t*)(ctx + (size_t)row0 * HH + col) =
            pack_f16(o[ni][0] * il, o[ni][1] * il);
        *(uint32_t*)(ctx + (size_t)(row0 + 8) * HH + col) =
            pack_f16(o[ni][2] * ih, o[ni][3] * ih);
    }
}

// ============================================================================
// LayerNorm: one warp per row (R10-proven)
// ============================================================================
__global__ __launch_bounds__(256)
void layernorm_warp_kernel(const float* __restrict__ x, const float* __restrict__ gamma,
                           const float* __restrict__ beta, float* __restrict__ out)
{
    const int w = threadIdx.x >> 5;
    const int lane = threadIdx.x & 31;
    const int row = blockIdx.x * 8 + w;

    const float4* xp = (const float4*)(x + (size_t)row * HH);
    float4 v[8];
    float s = 0.0f, s2 = 0.0f;
#pragma unroll
    for (int i = 0; i < 8; i++) {
        v[i] = xp[lane + i * 32];
        s  += v[i].x + v[i].y + v[i].z + v[i].w;
        s2 += v[i].x * v[i].x + v[i].y * v[i].y + v[i].z * v[i].z + v[i].w * v[i].w;
    }
#pragma unroll
    for (int o = 16; o > 0; o >>= 1) {
        s  += __shfl_xor_sync(~0u, s, o);
        s2 += __shfl_xor_sync(~0u, s2, o);
    }
    const float mu = s * (1.0f / HH);
    const float var = s2 * (1.0f / HH) - mu * mu;
    const float rstd = rsqrtf(var + 1e-5f);

    const float4* gp = (const float4*)gamma;
    const float4* bp = (const float4*)beta;
    float4* op = (float4*)(out + (size_t)row * HH);
#pragma unroll
    for (int i = 0; i < 8; i++) {
        const float4 gm = gp[lane + i * 32];
        const float4 bt = bp[lane + i * 32];
        float4 o;
        o.x = (v[i].x - mu) * rstd * gm.x + bt.x;
        o.y = (v[i].y - mu) * rstd * gm.y + bt.y;
        o.z = (v[i].z - mu) * rstd * gm.z + bt.z;
        o.w = (v[i].w - mu) * rstd * gm.w + bt.w;
        op[lane + i * 32] = o;
    }
}

// ============================================================================
extern "C" void kernel_launch(void* const* d_in, const int* in_sizes, int n_in,
                              void* d_out, int out_size)
{
    const float* hidden  = (const float*)d_in[0];
    const float* w_qkv   = (const float*)d_in[1];
    const float* b_qkv   = (const float*)d_in[2];
    const float* w_dense = (const float*)d_in[3];
    const float* b_dense = (const float*)d_in[4];
    const float* gamma   = (const float*)d_in[5];
    const float* beta    = (const float*)d_in[6];
    float* out = (float*)d_out;

    __half *hid, *wq, *wd, *qkv, *ctx;
    float* x;
    cudaGetSymbolAddress((void**)&hid, g_hid_h);
    cudaGetSymbolAddress((void**)&wq,  g_wq_h);
    cudaGetSymbolAddress((void**)&wd,  g_wd_h);
    cudaGetSymbolAddress((void**)&qkv, g_qkv_h);
    cudaGetSymbolAddress((void**)&ctx, g_ctx_h);
    cudaGetSymbolAddress((void**)&x,   g_x);

    // 0) all fp32 -> fp16 conversions, one launch, 4 float4/thread
    f2h_all_kernel<<<2048, 256>>>(hidden, w_qkv, w_dense, hid, wq, wd);

    // 1) QKV projection (128x256 tile, 4-stage, prefetch-after-compute)
    cudaFuncSetAttribute(gemm_f16_kernel<true>,
                         cudaFuncAttributeMaxDynamicSharedMemorySize, GEMM_SMEM_BYTES);
    gemm_f16_kernel<true><<<dim3(NQKV / 256, MTOT / 128), 256, GEMM_SMEM_BYTES>>>(
        hid, wq, b_qkv, nullptr, qkv, HH, NQKV);

    // 2) Flash attention
    cudaFuncSetAttribute(attn_f16_kernel,
                         cudaFuncAttributeMaxDynamicSharedMemorySize, ATTN_SMEM_BYTES);
    attn_f16_kernel<<<dim3(32, 16), 256, ATTN_SMEM_BYTES>>>(qkv, ctx);

    // 3) Dense projection (same config) + bias + residual
    cudaFuncSetAttribute(gemm_f16_kernel<false>,
                         cudaFuncAttributeMaxDynamicSharedMemorySize, GEMM_SMEM_BYTES);
    gemm_f16_kernel<false><<<dim3(HH / 256, MTOT / 128), 256, GEMM_SMEM_BYTES>>>(
        ctx, wd, b_dense, hidden, x, HH, HH);

    // 4) LayerNorm (one warp per row)
    layernorm_warp_kernel<<<MTOT / 8, 256>>>(x, gamma, beta, out);
}

// round 16
// speedup vs baseline: 1.1451x; 1.0417x over previous
#include <cuda_runtime.h>
#include <cuda_fp16.h>
#include <cstdint>
#include <math.h>

#define BB 2
#define SS 2048
#define HH 1024
#define NHEADS 16
#define HDIM 64
#define MTOT (BB*SS)      // 4096
#define NQKV (3*HH)       // 3072

// Scratch (allocation-free rule: __device__ globals)
__device__ __half g_hid_h[(size_t)MTOT * HH];    // 8 MiB
__device__ __half g_wq_h[(size_t)HH * NQKV];     // 6 MiB
__device__ __half g_wd_h[(size_t)HH * HH];       // 2 MiB
__device__ __half g_qkv_h[(size_t)MTOT * NQKV];  // 24 MiB (Q pre-scaled 0.125*log2e)
__device__ __half g_ctx_h[(size_t)MTOT * HH];    // 8 MiB
__device__ float g_x[(size_t)MTOT * HH];         // 16 MiB

// ============================================================================
// helpers
// ============================================================================
__device__ __forceinline__ uint32_t smem_u32(const void* p) {
    uint32_t a;
    asm("{ .reg .u64 t; cvta.to.shared.u64 t, %1; cvt.u32.u64 %0, t; }"
        : "=r"(a) : "l"(p));
    return a;
}
__device__ __forceinline__ void cpasync16(uint32_t s, const void* g) {
    asm volatile("cp.async.cg.shared.global [%0], [%1], 16;" :: "r"(s), "l"(g));
}
#define CP_COMMIT() asm volatile("cp.async.commit_group;" ::: "memory")
#define CP_WAIT0()  asm volatile("cp.async.wait_group 0;" ::: "memory")
#define CP_WAIT1()  asm volatile("cp.async.wait_group 1;" ::: "memory")
#define CP_WAIT2()  asm volatile("cp.async.wait_group 2;" ::: "memory")

// pack two f32 -> f16x2 (lo = first arg, hi = second arg)
__device__ __forceinline__ uint32_t pack_f16(float lo, float hi) {
    uint32_t r;
    asm("cvt.rn.f16x2.f32 %0, %1, %2;" : "=r"(r) : "f"(hi), "f"(lo));
    return r;
}
// fp16 m16n8k16, fp32 accumulate (all GEMMs + attention)
__device__ __forceinline__ void mma_f16_f32(float c[4], const uint32_t a[4],
                                            const uint32_t b[2]) {
    asm volatile(
        "mma.sync.aligned.m16n8k16.row.col.f32.f16.f16.f32 "
        "{%0,%1,%2,%3}, {%4,%5,%6,%7}, {%8,%9}, {%0,%1,%2,%3};\n"
        : "+f"(c[0]), "+f"(c[1]), "+f"(c[2]), "+f"(c[3])
        : "r"(a[0]), "r"(a[1]), "r"(a[2]), "r"(a[3]), "r"(b[0]), "r"(b[1]));
}
__device__ __forceinline__ void ldmatrix_x4(uint32_t r[4], uint32_t addr) {
    asm volatile("ldmatrix.sync.aligned.m8n8.x4.shared.b16 {%0,%1,%2,%3}, [%4];"
                 : "=r"(r[0]), "=r"(r[1]), "=r"(r[2]), "=r"(r[3]) : "r"(addr));
}
__device__ __forceinline__ void ldmatrix_x4t(uint32_t r[4], uint32_t addr) {
    asm volatile("ldmatrix.sync.aligned.m8n8.x4.trans.shared.b16 {%0,%1,%2,%3}, [%4];"
                 : "=r"(r[0]), "=r"(r[1]), "=r"(r[2]), "=r"(r[3]) : "r"(addr));
}

// ============================================================================
// prep: single-launch fp32 -> fp16 convert, 4 float4 per thread (MLP=4)
// blocks [0,1024): hidden, [1024,1792): w_qkv, [1792,2048): w_dense
// ============================================================================
__global__ __launch_bounds__(256)
void f2h_all_kernel(const float* __restrict__ hid_f, const float* __restrict__ wq_f,
                    const float* __restrict__ wd_f, __half* __restrict__ hid_h,
                    __half* __restrict__ wq_h, __half* __restrict__ wd_h)
{
    const int b = blockIdx.x;
    const float* in;
    __half* out;
    int rb;
    if (b < 1024)      { in = hid_f; out = hid_h; rb = b; }
    else if (b < 1792) { in = wq_f;  out = wq_h;  rb = b - 1024; }
    else               { in = wd_f;  out = wd_h;  rb = b - 1792; }

    float4 v[4];
#pragma unroll
    for (int i = 0; i < 4; i++)
        v[i] = ((const float4*)in)[(size_t)rb * 1024 + i * 256 + threadIdx.x];
#pragma unroll
    for (int i = 0; i < 4; i++) {
        uint2 o;
        o.x = pack_f16(v[i].x, v[i].y);
        o.y = pack_f16(v[i].z, v[i].w);
        ((uint2*)out)[(size_t)rb * 1024 + i * 256 + threadIdx.x] = o;
    }
}

// ============================================================================
// GEMM (R15-proven): 128x256 CTA tile, BK=64, 256 threads (8 warps as 2x4 of
// 64x64), 4-stage cp.async ring, prefetch after compute (race-free).
// QKV variant: out fp16, +bias, Q cols scaled by 0.125*log2(e) (exp2 domain).
// Dense variant: out fp32, +bias, +residual.
// ============================================================================
#define AS_STR 72
#define BS_STR 264
#define AS_ELE (128 * AS_STR)
#define BS_ELE (64 * BS_STR)
#define STAGE_ELE (AS_ELE + BS_ELE)            // 26112
#define GEMM_SMEM_BYTES (4 * STAGE_ELE * 2)    // 208896

#define QSCALE 0.18033688011112042f   // 0.125 * log2(e)

template<bool QKV>
__global__ __launch_bounds__(256)
void gemm_f16_kernel(const __half* __restrict__ A, const __half* __restrict__ B,
                     const float* __restrict__ bias, const float* __restrict__ res,
                     void* __restrict__ Cout, int K, int N)
{
    extern __shared__ __align__(16) __half sh[];

    const int tid = threadIdx.x;
    const int w = tid >> 5, lane = tid & 31;
    const int g = lane >> 2, tig = lane & 3;
    const int wm = w >> 2;
    const int wn = w & 3;
    const int bm = blockIdx.y * 128, bn = blockIdx.x * 256;
    const int nst = K / 64;

    float cf[4][8][4];
#pragma unroll
    for (int mi = 0; mi < 4; mi++)
#pragma unroll
        for (int ni = 0; ni < 8; ni++)
#pragma unroll
            for (int q = 0; q < 4; q++) cf[mi][ni][q] = 0.0f;

    auto load_stage = [&](int st, int ks) {
        __half* As = sh + st * STAGE_ELE;
        __half* Bs = As + AS_ELE;
#pragma unroll
        for (int i = 0; i < 4; i++) {
            int l = tid + i * 256;
            int row = l >> 3, seg = l & 7;
            cpasync16(smem_u32(As + row * AS_STR + seg * 8),
                      A + (size_t)(bm + row) * K + ks * 64 + seg * 8);
        }
#pragma unroll
        for (int i = 0; i < 8; i++) {
            int l = tid + i * 256;
            int row = l >> 5, seg = l & 31;
            cpasync16(smem_u32(Bs + row * BS_STR + seg * 8),
                      B + (size_t)(ks * 64 + row) * N + bn + seg * 8);
        }
    };

    load_stage(0, 0); CP_COMMIT();
    load_stage(1, 1); CP_COMMIT();
    load_stage(2, 2); CP_COMMIT();

    const int l16 = lane & 15;
    const int lhi = (lane >> 4) * 8;

    for (int ks = 0; ks < nst; ks++) {
        if (ks <= nst - 3)      { CP_WAIT2(); }
        else if (ks == nst - 2) { CP_WAIT1(); }
        else                    { CP_WAIT0(); }
        __syncthreads();

        const __half* Ab = sh + (ks & 3) * STAGE_ELE;
        const __half* Bb = Ab + AS_ELE;
#pragma unroll
        for (int kc = 0; kc < 4; kc++) {
            uint32_t au[4][4];
#pragma unroll
            for (int mi = 0; mi < 4; mi++)
                ldmatrix_x4(au[mi], smem_u32(Ab + (wm * 64 + mi * 16 + l16) * AS_STR
                                             + kc * 16 + lhi));
            uint32_t bu[8][2];
#pragma unroll
            for (int p = 0; p < 4; p++) {
                uint32_t t4[4];
                ldmatrix_x4t(t4, smem_u32(Bb + (kc * 16 + l16) * BS_STR
                                          + wn * 64 + p * 16 + lhi));
                bu[2 * p][0] = t4[0]; bu[2 * p][1] = t4[1];
                bu[2 * p + 1][0] = t4[2]; bu[2 * p + 1][1] = t4[3];
            }
#pragma unroll
            for (int mi = 0; mi < 4; mi++)
#pragma unroll
                for (int ni = 0; ni < 8; ni++)
                    mma_f16_f32(cf[mi][ni], au[mi], bu[ni]);
        }

        if (ks + 3 < nst) { load_stage((ks + 3) & 3, ks + 3); CP_COMMIT(); }
    }

#pragma unroll
    for (int mi = 0; mi < 4; mi++) {
        const int r = bm + wm * 64 + mi * 16 + g;
#pragma unroll
        for (int ni = 0; ni < 8; ni++) {
            const int c = bn + wn * 64 + ni * 8 + 2 * tig;
            float v0 = cf[mi][ni][0] + bias[c];
            float v1 = cf[mi][ni][1] + bias[c + 1];
            float v2 = cf[mi][ni][2] + bias[c];
            float v3 = cf[mi][ni][3] + bias[c + 1];
            if (QKV) {
                if ((c % 192) < 64) { v0 *= QSCALE; v1 *= QSCALE; v2 *= QSCALE; v3 *= QSCALE; }
                __half* Ch = (__half*)Cout;
                *(uint32_t*)(Ch + (size_t)r * N + c) = pack_f16(v0, v1);
                *(uint32_t*)(Ch + (size_t)(r + 8) * N + c) = pack_f16(v2, v3);
            } else {
                float* Cf = (float*)Cout;
                const float2 r0 = *(const float2*)(res + (size_t)r * N + c);
                const float2 r1 = *(const float2*)(res + (size_t)(r + 8) * N + c);
                *(float2*)(Cf + (size_t)r * N + c) = make_float2(v0 + r0.x, v1 + r0.y);
                *(float2*)(Cf + (size_t)(r + 8) * N + c) = make_float2(v2 + r1.x, v3 + r1.y);
            }
        }
    }
}

// ============================================================================
// Flash attention v2: 256 q-rows/CTA, each warp owns 32 rows (2 m-tiles) x
// all 64 keys — 32 LDSM per 128 MMAs per kt (R11 ratio). exp2-domain softmax
// (Q pre-scaled by 0.125*log2e). 4-stage KV ring, prefetch after compute.
// ============================================================================
#define TS 72
#define ATTN_Q_ROWS 256
#define ATTN_Q_ELE (ATTN_Q_ROWS * TS)          // 18432 halves
#define ATTN_KV_ELE (64 * TS)
#define ATTN_STAGE_ELE (2 * ATTN_KV_ELE)
#define ATTN_SMEM_BYTES ((ATTN_Q_ELE + 4 * ATTN_STAGE_ELE) * 2)  // 110592

__global__ __launch_bounds__(256, 1)
void attn_f16_kernel(const __half* __restrict__ qkv, __half* __restrict__ ctx)
{
    extern __shared__ __align__(16) __half sha[];
    __half* Qs = sha;
    __half* KV = sha + ATTN_Q_ELE;

    const int bh = blockIdx.x, qt = blockIdx.y;   // 32 x 8
    const int b = bh >> 4, h = bh & 15;
    const __half* base = qkv + (size_t)b * SS * NQKV + h * (3 * HDIM);

    const int tid = threadIdx.x;
    const int w = tid >> 5, lane = tid & 31;
    const int g = lane >> 2, tig = lane & 3;
    const int l16 = lane & 15;
    const int lhi = (lane >> 4) * 8;

    auto load_kv = [&](int kt, int st) {
        __half* Ks = KV + st * ATTN_STAGE_ELE;
        __half* Vs = Ks + ATTN_KV_ELE;
#pragma unroll
        for (int i = 0; i < 2; i++) {
            int l = tid + i * 256;
            int row = l >> 3, seg = l & 7;
            const __half* gp = base + (size_t)(kt * 64 + row) * NQKV + seg * 8;
            cpasync16(smem_u32(Ks + row * TS + seg * 8), gp + HDIM);
            cpasync16(smem_u32(Vs + row * TS + seg * 8), gp + 2 * HDIM);
        }
    };

    // Q tile: 256 rows x 64 cols
#pragma unroll
    for (int i = 0; i < 8; i++) {
        int l = tid + i * 256;
        int row = l >> 3, seg = l & 7;
        cpasync16(smem_u32(Qs + row * TS + seg * 8),
                  base + (size_t)(qt * 256 + row) * NQKV + seg * 8);
    }
    load_kv(0, 0); CP_COMMIT();
    load_kv(1, 1); CP_COMMIT();
    load_kv(2, 2); CP_COMMIT();

    uint32_t qf[2][4][4];
    float o[2][8][4];
#pragma unroll
    for (int mi = 0; mi < 2; mi++)
#pragma unroll
        for (int ni = 0; ni < 8; ni++)
#pragma unroll
            for (int q = 0; q < 4; q++) o[mi][ni][q] = 0.0f;
    float m[2][2] = {{-1e30f, -1e30f}, {-1e30f, -1e30f}};
    float lsum[2][2] = {{0.0f, 0.0f}, {0.0f, 0.0f}};

    for (int kt = 0; kt < 32; kt++) {
        if (kt <= 29)      { CP_WAIT2(); }
        else if (kt == 30) { CP_WAIT1(); }
        else               { CP_WAIT0(); }
        __syncthreads();

        if (kt == 0) {
#pragma unroll
            for (int mi = 0; mi < 2; mi++)
#pragma unroll
                for (int kc = 0; kc < 4; kc++)
                    ldmatrix_x4(qf[mi][kc],
                                smem_u32(Qs + (w * 32 + mi * 16 + l16) * TS
                                         + kc * 16 + lhi));
        }

        const __half* Kb = KV + (kt & 3) * ATTN_STAGE_ELE;
        const __half* Vb = Kb + ATTN_KV_ELE;

        // ---- S = Q K^T (exp2 domain): 16 LDSM, 64 MMAs ----
        float sfr[2][8][4];
#pragma unroll
        for (int mi = 0; mi < 2; mi++)
#pragma unroll
            for (int ni = 0; ni < 8; ni++)
#pragma unroll
                for (int q = 0; q < 4; q++) sfr[mi][ni][q] = 0.0f;
#pragma unroll
        for (int kc = 0; kc < 4; kc++) {
            uint32_t kf[4][4];
#pragma unroll
            for (int p = 0; p < 4; p++)
                ldmatrix_x4(kf[p],
                            smem_u32(Kb + (p * 16 + ((lane >> 4) << 3) + (lane & 7)) * TS
                                     + kc * 16 + (((lane >> 3) & 1) << 3)));
#pragma unroll
            for (int mi = 0; mi < 2; mi++)
#pragma unroll
                for (int p = 0; p < 4; p++) {
                    mma_f16_f32(sfr[mi][2 * p],     qf[mi][kc], &kf[p][0]);
                    mma_f16_f32(sfr[mi][2 * p + 1], qf[mi][kc], &kf[p][2]);
                }
        }

        // ---- online softmax per m-tile (exp2) ----
        uint32_t pu[2][4][4];
#pragma unroll
        for (int mi = 0; mi < 2; mi++) {
            float tl = -1e30f, th = -1e30f;
#pragma unroll
            for (int ni = 0; ni < 8; ni++) {
                tl = fmaxf(tl, fmaxf(sfr[mi][ni][0], sfr[mi][ni][1]));
                th = fmaxf(th, fmaxf(sfr[mi][ni][2], sfr[mi][ni][3]));
            }
            tl = fmaxf(tl, __shfl_xor_sync(0xffffffffu, tl, 1));
            tl = fmaxf(tl, __shfl_xor_sync(0xffffffffu, tl, 2));
            th = fmaxf(th, __shfl_xor_sync(0xffffffffu, th, 1));
            th = fmaxf(th, __shfl_xor_sync(0xffffffffu, th, 2));

            const float mnl = fmaxf(m[mi][0], tl), mnh = fmaxf(m[mi][1], th);
            const float al = exp2f(m[mi][0] - mnl), ah = exp2f(m[mi][1] - mnh);
            m[mi][0] = mnl; m[mi][1] = mnh;

            float sl = 0.0f, shi = 0.0f;
#pragma unroll
            for (int ni = 0; ni < 8; ni++) {
                sfr[mi][ni][0] = exp2f(sfr[mi][ni][0] - mnl);
                sfr[mi][ni][1] = exp2f(sfr[mi][ni][1] - mnl);
                sfr[mi][ni][2] = exp2f(sfr[mi][ni][2] - mnh);
                sfr[mi][ni][3] = exp2f(sfr[mi][ni][3] - mnh);
                sl  += sfr[mi][ni][0] + sfr[mi][ni][1];
                shi += sfr[mi][ni][2] + sfr[mi][ni][3];
            }
            lsum[mi][0] = lsum[mi][0] * al + sl;
            lsum[mi][1] = lsum[mi][1] * ah + shi;
#pragma unroll
            for (int ni = 0; ni < 8; ni++) {
                o[mi][ni][0] *= al; o[mi][ni][1] *= al;
                o[mi][ni][2] *= ah; o[mi][ni][3] *= ah;
            }
#pragma unroll
            for (int j = 0; j < 4; j++) {
                pu[mi][j][0] = pack_f16(sfr[mi][2 * j][0],     sfr[mi][2 * j][1]);
                pu[mi][j][1] = pack_f16(sfr[mi][2 * j][2],     sfr[mi][2 * j][3]);
                pu[mi][j][2] = pack_f16(sfr[mi][2 * j + 1][0], sfr[mi][2 * j + 1][1]);
                pu[mi][j][3] = pack_f16(sfr[mi][2 * j + 1][2], sfr[mi][2 * j + 1][3]);
            }
        }

        // ---- O += P V: 16 LDSM, 64 MMAs ----
#pragma unroll
        for (int kc = 0; kc < 4; kc++) {
            uint32_t vf[4][4];
#pragma unroll
            for (int p = 0; p < 4; p++)
                ldmatrix_x4t(vf[p], smem_u32(Vb + (kc * 16 + l16) * TS + p * 16 + lhi));
#pragma unroll
            for (int mi = 0; mi < 2; mi++)
#pragma unroll
                for (int p = 0; p < 4; p++) {
                    mma_f16_f32(o[mi][2 * p],     pu[mi][kc], &vf[p][0]);
                    mma_f16_f32(o[mi][2 * p + 1], pu[mi][kc], &vf[p][2]);
                }
        }

        if (kt + 3 < 32) { load_kv(kt + 3, (kt + 3) & 3); CP_COMMIT(); }
    }

    // finalize + store
#pragma unroll
    for (int mi = 0; mi < 2; mi++) {
        float l0 = lsum[mi][0], l1 = lsum[mi][1];
        l0 += __shfl_xor_sync(0xffffffffu, l0, 1);
        l0 += __shfl_xor_sync(0xffffffffu, l0, 2);
        l1 += __shfl_xor_sync(0xffffffffu, l1, 1);
        l1 += __shfl_xor_sync(0xffffffffu, l1, 2);
        const float il = 1.0f / l0, ih = 1.0f / l1;

        const int row0 = b * SS + qt * 256 + w * 32 + mi * 16 + g;
#pragma unroll
        for (int ni = 0; ni < 8; ni++) {
            const int col = h * HDIM + ni * 8 + 2 * tig;
            *(uint32_t*)(ctx + (size_t)row0 * HH + col) =
                pack_f16(o[mi][ni][0] * il, o[mi][ni][1] * il);
            *(uint32_t*)(ctx + (size_t)(row0 + 8) * HH + col) =
                pack_f16(o[mi][ni][2] * ih, o[mi][ni][3] * ih);
        }
    }
}

// ============================================================================
// LayerNorm: one warp per row (R10-proven)
// ============================================================================
__global__ __launch_bounds__(256)
void layernorm_warp_kernel(const float* __restrict__ x, const float* __restrict__ gamma,
                           const float* __restrict__ beta, float* __restrict__ out)
{
    const int w = threadIdx.x >> 5;
    const int lane = threadIdx.x & 31;
    const int row = blockIdx.x * 8 + w;

    const float4* xp = (const float4*)(x + (size_t)row * HH);
    float4 v[8];
    float s = 0.0f, s2 = 0.0f;
#pragma unroll
    for (int i = 0; i < 8; i++) {
        v[i] = xp[lane + i * 32];
        s  += v[i].x + v[i].y + v[i].z + v[i].w;
        s2 += v[i].x * v[i].x + v[i].y * v[i].y + v[i].z * v[i].z + v[i].w * v[i].w;
    }
#pragma unroll
    for (int o = 16; o > 0; o >>= 1) {
        s  += __shfl_xor_sync(~0u, s, o);
        s2 += __shfl_xor_sync(~0u, s2, o);
    }
    const float mu = s * (1.0f / HH);
    const float var = s2 * (1.0f / HH) - mu * mu;
    const float rstd = rsqrtf(var + 1e-5f);

    const float4* gp = (const float4*)gamma;
    const float4* bp = (const float4*)beta;
    float4* op = (float4*)(out + (size_t)row * HH);
#pragma unroll
    for (int i = 0; i < 8; i++) {
        const float4 gm = gp[lane + i * 32];
        const float4 bt = bp[lane + i * 32];
        float4 o;
        o.x = (v[i].x - mu) * rstd * gm.x + bt.x;
        o.y = (v[i].y - mu) * rstd * gm.y + bt.y;
        o.z = (v[i].z - mu) * rstd * gm.z + bt.z;
        o.w = (v[i].w - mu) * rstd * gm.w + bt.w;
        op[lane + i * 32] = o;
    }
}

// ============================================================================
extern "C" void kernel_launch(void* const* d_in, const int* in_sizes, int n_in,
                              void* d_out, int out_size)
{
    const float* hidden  = (const float*)d_in[0];
    const float* w_qkv   = (const float*)d_in[1];
    const float* b_qkv   = (const float*)d_in[2];
    const float* w_dense = (const float*)d_in[3];
    const float* b_dense = (const float*)d_in[4];
    const float* gamma   = (const float*)d_in[5];
    const float* beta    = (const float*)d_in[6];
    float* out = (float*)d_out;

    __half *hid, *wq, *wd, *qkv, *ctx;
    float* x;
    cudaGetSymbolAddress((void**)&hid, g_hid_h);
    cudaGetSymbolAddress((void**)&wq,  g_wq_h);
    cudaGetSymbolAddress((void**)&wd,  g_wd_h);
    cudaGetSymbolAddress((void**)&qkv, g_qkv_h);
    cudaGetSymbolAddress((void**)&ctx, g_ctx_h);
    cudaGetSymbolAddress((void**)&x,   g_x);

    // 0) all fp32 -> fp16 conversions, one launch, 4 float4/thread
    f2h_all_kernel<<<2048, 256>>>(hidden, w_qkv, w_dense, hid, wq, wd);

    // 1) QKV projection (128x256 tile, 4-stage) -> fp16, Q scaled 0.125*log2e
    cudaFuncSetAttribute(gemm_f16_kernel<true>,
                         cudaFuncAttributeMaxDynamicSharedMemorySize, GEMM_SMEM_BYTES);
    gemm_f16_kernel<true><<<dim3(NQKV / 256, MTOT / 128), 256, GEMM_SMEM_BYTES>>>(
        hid, wq, b_qkv, nullptr, qkv, HH, NQKV);

    // 2) Flash attention (256 q-rows/CTA, 32 rows/warp, exp2 softmax)
    cudaFuncSetAttribute(attn_f16_kernel,
                         cudaFuncAttributeMaxDynamicSharedMemorySize, ATTN_SMEM_BYTES);
    attn_f16_kernel<<<dim3(32, 8), 256, ATTN_SMEM_BYTES>>>(qkv, ctx);

    // 3) Dense projection (128x256 tile, 4-stage) + bias + residual
    cudaFuncSetAttribute(gemm_f16_kernel<false>,
                         cudaFuncAttributeMaxDynamicSharedMemorySize, GEMM_SMEM_BYTES);
    gemm_f16_kernel<false><<<dim3(HH / 256, MTOT / 128), 256, GEMM_SMEM_BYTES>>>(
        ctx, wd, b_dense, hidden, x, HH, HH);

    // 4) LayerNorm (one warp per row)
    layernorm_warp_kernel<<<MTOT / 8, 256>>>(x, gamma, beta, out);
}